// round 11
// baseline (speedup 1.0000x reference)
#include <cuda_runtime.h>

#define NUM_NET 2
#define V 100000
#define D 128
#define B 4096
#define K 5
#define NS 10

#define NTHREADS 256
#define WPB 8
#define NEIGH_WARPS 32768                  // 4 warps per (i,b), single-table phased
#define NODE_WARPS  8192                   // 1 warp per (m,b): 33 rows each, one wave
#define NEIGH_BLOCKS (NEIGH_WARPS / WPB)   // 4096
#define NODE_BLOCKS  (NODE_WARPS / WPB)    // 1024
#define NPART (NEIGH_BLOCKS + NODE_BLOCKS) // 5120

__device__ float g_part[NPART];
__device__ int   g_count = 0;

__device__ __forceinline__ float logsig_fast(float x) {
    // log(sigmoid(x)) = min(x,0) - log(1 + exp(-|x|)); fast-math (err ~1e-6 vs 1e-3 budget)
    return fminf(x, 0.0f) - __logf(1.0f + __expf(-fabsf(x)));
}

__device__ __forceinline__ float dot4(float4 a, float4 b) {
    return fmaf(a.x, b.x, fmaf(a.y, b.y, fmaf(a.z, b.z, a.w * b.w)));
}

// Sum of logsig(sign*(row . ne)) over M rows, 5 independent chains per batch.
// The proven 32-reg shape. Do not touch.
template<bool NEG>
__device__ __forceinline__ float rows_sum5(const float* __restrict__ tab,
                                           const int* __restrict__ idx,
                                           int M, float4 ne, int lane) {
    float a = 0.0f;
    for (int m = 0; m < M; m += 5) {
        float4 c[5];
        #pragma unroll
        for (int u = 0; u < 5; u++) {
            int id = __ldg(idx + m + u);
            c[u] = __ldg(reinterpret_cast<const float4*>(tab + (size_t)id * D) + lane);
        }
        float s[5];
        #pragma unroll
        for (int u = 0; u < 5; u++) s[u] = dot4(ne, c[u]);
        #pragma unroll
        for (int off = 16; off; off >>= 1) {
            #pragma unroll
            for (int u = 0; u < 5; u++)
                s[u] += __shfl_xor_sync(0xffffffffu, s[u], off);
        }
        #pragma unroll
        for (int u = 0; u < 5; u++) a += logsig_fast(NEG ? -s[u] : s[u]);
    }
    return a;
}

__device__ __forceinline__ float pos2(const float* __restrict__ tab, int i0, int i1,
                                      float4 ne, int lane) {
    float4 c0 = __ldg(reinterpret_cast<const float4*>(tab + (size_t)i0 * D) + lane);
    float4 c1 = __ldg(reinterpret_cast<const float4*>(tab + (size_t)i1 * D) + lane);
    float s0 = dot4(ne, c0), s1 = dot4(ne, c1);
    #pragma unroll
    for (int off = 16; off; off >>= 1) {
        s0 += __shfl_xor_sync(0xffffffffu, s0, off);
        s1 += __shfl_xor_sync(0xffffffffu, s1, off);
    }
    return logsig_fast(s0) + logsig_fast(s1);
}

__device__ __forceinline__ float pos1(const float* __restrict__ tab, int i0,
                                      float4 ne, int lane) {
    float4 c0 = __ldg(reinterpret_cast<const float4*>(tab + (size_t)i0 * D) + lane);
    float s0 = dot4(ne, c0);
    #pragma unroll
    for (int off = 16; off; off >>= 1)
        s0 += __shfl_xor_sync(0xffffffffu, s0, off);
    return logsig_fast(s0);
}

__device__ __forceinline__ void block_publish(float acc, int lane, int wid, int slot) {
    __shared__ float sacc[WPB];
    if (lane == 0) sacc[wid] = acc;
    __syncthreads();
    if (threadIdx.x == 0) {
        float t = 0.0f;
        #pragma unroll
        for (int w = 0; w < WPB; w++) t += sacc[w];
        g_part[slot] = t;
    }
}

// ---------------- kernel 1: neigh-table terms (t1, t3) ----------------
__global__ void __launch_bounds__(NTHREADS)
neigh_kernel(const float* __restrict__ node_tables,
             const float* __restrict__ neigh_tables,
             const int* __restrict__ nodes_idx,
             const int* __restrict__ neigh_idx,
             const int* __restrict__ neg_main,
             const int* __restrict__ neg_cross) {
    const int lane = threadIdx.x & 31;
    const int wid  = threadIdx.x >> 5;
    const int gw   = blockIdx.x * WPB + wid;
    const size_t VD = (size_t)V * D;

    const float CB = 1.0f / (10.0f * (float)B);
    const float WH = 0.1f;

    // block-index ordered: first half targets gt0, second half gt1 -> one
    // 51MB table L2-resident per phase
    const int g   = gw >> 14;
    const int r   = gw & 16383;
    const int b   = r >> 2;
    const int sub = r & 3;

    const float* gt = neigh_tables + (size_t)g * VD;

    float acc = 0.0f;
    if (sub < 2) {
        // main SGNS of view i=g (weight 1)
        const int nid = __ldg(nodes_idx + g * B + b);
        const float4 ne = __ldg(reinterpret_cast<const float4*>(
            node_tables + (size_t)g * VD + (size_t)nid * D) + lane);
        const int* nm = neg_main + (size_t)(g * B + b) * (K * NS);
        if (sub == 0) {
            acc += rows_sum5<false>(gt, neigh_idx + (g * B + b) * K, K, ne, lane) * (-CB / (float)K);
            acc += rows_sum5<true>(gt, nm, 25, ne, lane) * (-CB);
        } else {
            acc += rows_sum5<true>(gt, nm + 25, 25, ne, lane) * (-CB);
        }
    } else {
        // cross neighbor loss of view i=1-g with j=g (weight HYP2)
        const int i = 1 - g;
        const int nid = __ldg(nodes_idx + i * B + b);
        const float4 ne = __ldg(reinterpret_cast<const float4*>(
            node_tables + (size_t)i * VD + (size_t)nid * D) + lane);
        const int* nc = neg_cross + (size_t)((i * NUM_NET + g) * B + b) * (K * NS);
        if (sub == 2) {
            acc += rows_sum5<false>(gt, neigh_idx + (i * B + b) * K, K, ne, lane) * (-WH * CB / (float)K);
            acc += rows_sum5<true>(gt, nc, 25, ne, lane) * (-WH * CB);
        } else {
            acc += rows_sum5<true>(gt, nc + 25, 25, ne, lane) * (-WH * CB);
        }
    }

    block_publish(acc, lane, wid, blockIdx.x);
}

// -------- kernel 2: node-table terms (t2, roles) + final reduction --------
// One warp per (m, b), 33 balanced rows all on node table m; 8192 warps = 1 wave.
__global__ void __launch_bounds__(NTHREADS)
node_kernel(const float* __restrict__ node_tables,
            const int* __restrict__ nodes_idx,
            const int* __restrict__ role_idx,
            const int* __restrict__ neg_node,
            const int* __restrict__ neg_role,
            float* __restrict__ out) {
    const int lane = threadIdx.x & 31;
    const int wid  = threadIdx.x >> 5;
    const int gw   = blockIdx.x * WPB + wid;   // 0 .. 8191
    const size_t VD = (size_t)V * D;

    const float CB = 1.0f / (10.0f * (float)B);
    const float WH = 0.1f;
    const float w  = -WH * CB;

    const int m = gw >> 12;          // target node table
    const int b = gw & 4095;

    const float* nt = node_tables + (size_t)m * VD;

    float acc = 0.0f;

    // --- section A: view iA = 1-m (t2 pos+10neg, role(iA,m) pos+10neg): 22 rows ---
    {
        const int iA = 1 - m;
        const int nid = __ldg(nodes_idx + iA * B + b);
        const float4 ne = __ldg(reinterpret_cast<const float4*>(
            node_tables + (size_t)iA * VD + (size_t)nid * D) + lane);

        const int rp = __ldg(role_idx + (iA * NUM_NET + m) * B + b);
        acc += pos2(nt, nid, rp, ne, lane) * w;
        acc += rows_sum5<true>(nt, neg_node + (size_t)((iA * NUM_NET + m) * B + b) * NS, NS, ne, lane) * w;
        acc += rows_sum5<true>(nt, neg_role + (size_t)((iA * NUM_NET + m) * B + b) * NS, NS, ne, lane) * w;
    }

    // --- section B: view iB = m (role(m,m) pos+10neg): 11 rows ---
    {
        const int iB = m;
        const int nid = __ldg(nodes_idx + iB * B + b);
        const float4 ne = __ldg(reinterpret_cast<const float4*>(
            node_tables + (size_t)iB * VD + (size_t)nid * D) + lane);

        const int rp = __ldg(role_idx + (iB * NUM_NET + m) * B + b);
        acc += pos1(nt, rp, ne, lane) * w;
        acc += rows_sum5<true>(nt, neg_role + (size_t)((iB * NUM_NET + m) * B + b) * NS, NS, ne, lane) * w;
    }

    block_publish(acc, lane, wid, NEIGH_BLOCKS + blockIdx.x);

    // last node-block reduces ALL partials (kernel-1 partials already globally
    // visible: kernel boundary). Fixed read order -> deterministic.
    __shared__ int s_last;
    if (threadIdx.x == 0) {
        __threadfence();
        int c = atomicAdd(&g_count, 1);
        s_last = (c == NODE_BLOCKS - 1);
    }
    __syncthreads();
    if (s_last) {
        __threadfence();
        __shared__ double sh[WPB];
        double t = 0.0;
        for (int k2 = threadIdx.x; k2 < NPART; k2 += NTHREADS)
            t += (double)g_part[k2];
        #pragma unroll
        for (int off = 16; off; off >>= 1)
            t += __shfl_xor_sync(0xffffffffu, t, off);
        if (lane == 0) sh[wid] = t;
        __syncthreads();
        if (threadIdx.x == 0) {
            double v = 0.0;
            #pragma unroll
            for (int ww = 0; ww < WPB; ww++) v += sh[ww];
            out[0] = (float)v;
            g_count = 0;              // reset for next graph replay
        }
    }
}

extern "C" void kernel_launch(void* const* d_in, const int* in_sizes, int n_in,
                              void* d_out, int out_size) {
    const float* node_tables  = (const float*)d_in[0];
    const float* neigh_tables = (const float*)d_in[1];
    const int*   nodes_idx    = (const int*)d_in[2];
    const int*   neigh_idx    = (const int*)d_in[3];
    const int*   role_idx     = (const int*)d_in[4];
    const int*   neg_main     = (const int*)d_in[5];
    const int*   neg_node     = (const int*)d_in[6];
    const int*   neg_cross    = (const int*)d_in[7];
    const int*   neg_role     = (const int*)d_in[8];

    (void)in_sizes; (void)n_in; (void)out_size;

    neigh_kernel<<<NEIGH_BLOCKS, NTHREADS>>>(node_tables, neigh_tables, nodes_idx,
                                             neigh_idx, neg_main, neg_cross);
    node_kernel<<<NODE_BLOCKS, NTHREADS>>>(node_tables, nodes_idx, role_idx,
                                           neg_node, neg_role, (float*)d_out);
}

// round 12
// speedup vs baseline: 1.0250x; 1.0250x over previous
#include <cuda_runtime.h>

#define NUM_NET 2
#define V 100000
#define D 128
#define B 4096
#define K 5
#define NS 10

#define NTHREADS 256
#define WPB 8
#define NEIGH_WARPS 32768                  // 4 warps per (i,b), single-table phased
#define NODE_WARPS  24576                  // 1 warp per 11-row unit, table-phased
#define NEIGH_BLOCKS (NEIGH_WARPS / WPB)   // 4096
#define NODE_BLOCKS  (NODE_WARPS / WPB)    // 3072
#define NPART (NEIGH_BLOCKS + NODE_BLOCKS) // 7168

__device__ float g_part[NPART];
__device__ int   g_count = 0;

__device__ __forceinline__ float logsig_fast(float x) {
    // log(sigmoid(x)) = min(x,0) - log(1 + exp(-|x|)); fast-math (err ~1e-6 vs 1e-3 budget)
    return fminf(x, 0.0f) - __logf(1.0f + __expf(-fabsf(x)));
}

__device__ __forceinline__ float dot4(float4 a, float4 b) {
    return fmaf(a.x, b.x, fmaf(a.y, b.y, fmaf(a.z, b.z, a.w * b.w)));
}

// Sum of logsig(sign*(row . ne)) over M rows, 5 independent chains per batch.
// The proven 32-reg shape. Do not touch.
template<bool NEG>
__device__ __forceinline__ float rows_sum5(const float* __restrict__ tab,
                                           const int* __restrict__ idx,
                                           int M, float4 ne, int lane) {
    float a = 0.0f;
    for (int m = 0; m < M; m += 5) {
        float4 c[5];
        #pragma unroll
        for (int u = 0; u < 5; u++) {
            int id = __ldg(idx + m + u);
            c[u] = __ldg(reinterpret_cast<const float4*>(tab + (size_t)id * D) + lane);
        }
        float s[5];
        #pragma unroll
        for (int u = 0; u < 5; u++) s[u] = dot4(ne, c[u]);
        #pragma unroll
        for (int off = 16; off; off >>= 1) {
            #pragma unroll
            for (int u = 0; u < 5; u++)
                s[u] += __shfl_xor_sync(0xffffffffu, s[u], off);
        }
        #pragma unroll
        for (int u = 0; u < 5; u++) a += logsig_fast(NEG ? -s[u] : s[u]);
    }
    return a;
}

__device__ __forceinline__ float pos1(const float* __restrict__ tab, int i0,
                                      float4 ne, int lane) {
    float4 c0 = __ldg(reinterpret_cast<const float4*>(tab + (size_t)i0 * D) + lane);
    float s0 = dot4(ne, c0);
    #pragma unroll
    for (int off = 16; off; off >>= 1)
        s0 += __shfl_xor_sync(0xffffffffu, s0, off);
    return logsig_fast(s0);
}

__device__ __forceinline__ void block_publish(float acc, int lane, int wid, int slot) {
    __shared__ float sacc[WPB];
    if (lane == 0) sacc[wid] = acc;
    __syncthreads();
    if (threadIdx.x == 0) {
        float t = 0.0f;
        #pragma unroll
        for (int w = 0; w < WPB; w++) t += sacc[w];
        g_part[slot] = t;
    }
}

// ---------------- kernel 1: neigh-table terms (t1, t3) ----------------
__global__ void __launch_bounds__(NTHREADS)
neigh_kernel(const float* __restrict__ node_tables,
             const float* __restrict__ neigh_tables,
             const int* __restrict__ nodes_idx,
             const int* __restrict__ neigh_idx,
             const int* __restrict__ neg_main,
             const int* __restrict__ neg_cross) {
    const int lane = threadIdx.x & 31;
    const int wid  = threadIdx.x >> 5;
    const int gw   = blockIdx.x * WPB + wid;
    const size_t VD = (size_t)V * D;

    const float CB = 1.0f / (10.0f * (float)B);
    const float WH = 0.1f;

    // block-index ordered: first half targets gt0, second half gt1 -> one
    // 51MB table L2-resident per phase
    const int g   = gw >> 14;
    const int r   = gw & 16383;
    const int b   = r >> 2;
    const int sub = r & 3;

    const float* gt = neigh_tables + (size_t)g * VD;

    float acc = 0.0f;
    if (sub < 2) {
        // main SGNS of view i=g (weight 1)
        const int nid = __ldg(nodes_idx + g * B + b);
        const float4 ne = __ldg(reinterpret_cast<const float4*>(
            node_tables + (size_t)g * VD + (size_t)nid * D) + lane);
        const int* nm = neg_main + (size_t)(g * B + b) * (K * NS);
        if (sub == 0) {
            acc += rows_sum5<false>(gt, neigh_idx + (g * B + b) * K, K, ne, lane) * (-CB / (float)K);
            acc += rows_sum5<true>(gt, nm, 25, ne, lane) * (-CB);
        } else {
            acc += rows_sum5<true>(gt, nm + 25, 25, ne, lane) * (-CB);
        }
    } else {
        // cross neighbor loss of view i=1-g with j=g (weight HYP2)
        const int i = 1 - g;
        const int nid = __ldg(nodes_idx + i * B + b);
        const float4 ne = __ldg(reinterpret_cast<const float4*>(
            node_tables + (size_t)i * VD + (size_t)nid * D) + lane);
        const int* nc = neg_cross + (size_t)((i * NUM_NET + g) * B + b) * (K * NS);
        if (sub == 2) {
            acc += rows_sum5<false>(gt, neigh_idx + (i * B + b) * K, K, ne, lane) * (-WH * CB / (float)K);
            acc += rows_sum5<true>(gt, nc, 25, ne, lane) * (-WH * CB);
        } else {
            acc += rows_sum5<true>(gt, nc + 25, 25, ne, lane) * (-WH * CB);
        }
    }

    block_publish(acc, lane, wid, blockIdx.x);
}

// -------- kernel 2: node-table units (t2, roles) + final reduction --------
// One warp per 11-row unit (pos + 10 negs, all on a single node table).
// 24576 warps = 2.6 waves, perfectly balanced; block-ordered by target table.
__global__ void __launch_bounds__(NTHREADS)
node_kernel(const float* __restrict__ node_tables,
            const int* __restrict__ nodes_idx,
            const int* __restrict__ role_idx,
            const int* __restrict__ neg_node,
            const int* __restrict__ neg_role,
            float* __restrict__ out) {
    const int lane = threadIdx.x & 31;
    const int wid  = threadIdx.x >> 5;
    const int gw   = blockIdx.x * WPB + wid;   // 0 .. 24575
    const size_t VD = (size_t)V * D;

    const float CB = 1.0f / (10.0f * (float)B);
    const float w  = -0.1f * CB;               // all node-side terms carry HYP*CB

    const int t   = gw / 12288;                // target node table
    const int u   = gw - t * 12288;
    const int seg = u >> 12;                   // 0: t2-unit, 1: role(i=0), 2: role(i=1)
    const int b   = u & 4095;

    const float* nt = node_tables + (size_t)t * VD;

    int i, posid;
    const int* negp;
    if (seg == 0) {
        // t2 unit: view i = 1-t reads node table t at its own node index
        i = 1 - t;
        posid = __ldg(nodes_idx + i * B + b);
        negp  = neg_node + (size_t)((i * NUM_NET + t) * B + b) * NS;
    } else {
        // role unit: view i = seg-1, j2 = t
        i = seg - 1;
        posid = __ldg(role_idx + (i * NUM_NET + t) * B + b);
        negp  = neg_role + (size_t)((i * NUM_NET + t) * B + b) * NS;
    }

    const int nid = __ldg(nodes_idx + i * B + b);
    const float4 ne = __ldg(reinterpret_cast<const float4*>(
        node_tables + (size_t)i * VD + (size_t)nid * D) + lane);

    float acc = pos1(nt, posid, ne, lane) * w;
    acc += rows_sum5<true>(nt, negp, NS, ne, lane) * w;

    block_publish(acc, lane, wid, NEIGH_BLOCKS + blockIdx.x);

    // last node-block reduces ALL partials (kernel-1 partials already globally
    // visible: kernel boundary). Fixed read order -> deterministic.
    __shared__ int s_last;
    if (threadIdx.x == 0) {
        __threadfence();
        int c = atomicAdd(&g_count, 1);
        s_last = (c == NODE_BLOCKS - 1);
    }
    __syncthreads();
    if (s_last) {
        __threadfence();
        __shared__ double sh[WPB];
        double td = 0.0;
        for (int k2 = threadIdx.x; k2 < NPART; k2 += NTHREADS)
            td += (double)g_part[k2];
        #pragma unroll
        for (int off = 16; off; off >>= 1)
            td += __shfl_xor_sync(0xffffffffu, td, off);
        if (lane == 0) sh[wid] = td;
        __syncthreads();
        if (threadIdx.x == 0) {
            double v = 0.0;
            #pragma unroll
            for (int ww = 0; ww < WPB; ww++) v += sh[ww];
            out[0] = (float)v;
            g_count = 0;              // reset for next graph replay
        }
    }
}

extern "C" void kernel_launch(void* const* d_in, const int* in_sizes, int n_in,
                              void* d_out, int out_size) {
    const float* node_tables  = (const float*)d_in[0];
    const float* neigh_tables = (const float*)d_in[1];
    const int*   nodes_idx    = (const int*)d_in[2];
    const int*   neigh_idx    = (const int*)d_in[3];
    const int*   role_idx     = (const int*)d_in[4];
    const int*   neg_main     = (const int*)d_in[5];
    const int*   neg_node     = (const int*)d_in[6];
    const int*   neg_cross    = (const int*)d_in[7];
    const int*   neg_role     = (const int*)d_in[8];

    (void)in_sizes; (void)n_in; (void)out_size;

    neigh_kernel<<<NEIGH_BLOCKS, NTHREADS>>>(node_tables, neigh_tables, nodes_idx,
                                             neigh_idx, neg_main, neg_cross);
    node_kernel<<<NODE_BLOCKS, NTHREADS>>>(node_tables, nodes_idx, role_idx,
                                           neg_node, neg_role, (float*)d_out);
}

// round 13
// speedup vs baseline: 1.0287x; 1.0036x over previous
#include <cuda_runtime.h>

#define NUM_NET 2
#define V 100000
#define D 128
#define B 4096
#define K 5
#define NS 10

#define NTHREADS 256
#define WPB 8
#define NEIGH_WARPS 32768                  // 4 warps per (i,b), single-table phased
#define NODE_WARPS  16384                  // 1 warp per (i,b,m) -- R10 exact
#define NEIGH_BLOCKS (NEIGH_WARPS / WPB)   // 4096
#define NODE_BLOCKS  (NODE_WARPS / WPB)    // 2048
#define NPART (NEIGH_BLOCKS + NODE_BLOCKS) // 6144

__device__ float g_part[NPART];
__device__ int   g_count = 0;

__device__ __forceinline__ float logsig_fast(float x) {
    // log(sigmoid(x)) = min(x,0) - log(1 + exp(-|x|)); fast-math (err ~1e-6 vs 1e-3 budget)
    return fminf(x, 0.0f) - __logf(1.0f + __expf(-fabsf(x)));
}

__device__ __forceinline__ float dot4(float4 a, float4 b) {
    return fmaf(a.x, b.x, fmaf(a.y, b.y, fmaf(a.z, b.z, a.w * b.w)));
}

// ---------- float4 path (node kernel, R10-proven 32-reg shape) ----------
template<bool NEG>
__device__ __forceinline__ float rows_sum5(const float* __restrict__ tab,
                                           const int* __restrict__ idx,
                                           int M, float4 ne, int lane) {
    float a = 0.0f;
    for (int m = 0; m < M; m += 5) {
        float4 c[5];
        #pragma unroll
        for (int u = 0; u < 5; u++) {
            int id = __ldg(idx + m + u);
            c[u] = __ldg(reinterpret_cast<const float4*>(tab + (size_t)id * D) + lane);
        }
        float s[5];
        #pragma unroll
        for (int u = 0; u < 5; u++) s[u] = dot4(ne, c[u]);
        #pragma unroll
        for (int off = 16; off; off >>= 1) {
            #pragma unroll
            for (int u = 0; u < 5; u++)
                s[u] += __shfl_xor_sync(0xffffffffu, s[u], off);
        }
        #pragma unroll
        for (int u = 0; u < 5; u++) a += logsig_fast(NEG ? -s[u] : s[u]);
    }
    return a;
}

__device__ __forceinline__ float pos2(const float* __restrict__ tab, int i0, int i1,
                                      float4 ne, int lane) {
    float4 c0 = __ldg(reinterpret_cast<const float4*>(tab + (size_t)i0 * D) + lane);
    float4 c1 = __ldg(reinterpret_cast<const float4*>(tab + (size_t)i1 * D) + lane);
    float s0 = dot4(ne, c0), s1 = dot4(ne, c1);
    #pragma unroll
    for (int off = 16; off; off >>= 1) {
        s0 += __shfl_xor_sync(0xffffffffu, s0, off);
        s1 += __shfl_xor_sync(0xffffffffu, s1, off);
    }
    return logsig_fast(s0) + logsig_fast(s1);
}

__device__ __forceinline__ float pos1(const float* __restrict__ tab, int i0,
                                      float4 ne, int lane) {
    float4 c0 = __ldg(reinterpret_cast<const float4*>(tab + (size_t)i0 * D) + lane);
    float s0 = dot4(ne, c0);
    #pragma unroll
    for (int off = 16; off; off >>= 1)
        s0 += __shfl_xor_sync(0xffffffffu, s0, off);
    return logsig_fast(s0);
}

// ---------- float2-split path (neigh kernel): 2x LDG.64 per row ----------
// Each LDG spans 256B = 2 lines -> avoids the 2.07 cyc/wf within-LDG replay
// of a 4-line LDG.128.
template<bool NEG>
__device__ __forceinline__ float rows_sum5h(const float* __restrict__ tab,
                                            const int* __restrict__ idx,
                                            int M, float2 neA, float2 neB, int lane) {
    float a = 0.0f;
    for (int m = 0; m < M; m += 5) {
        float2 cA[5], cB[5];
        #pragma unroll
        for (int u = 0; u < 5; u++) {
            int id = __ldg(idx + m + u);
            const float* base = tab + (size_t)id * D + 2 * lane;
            cA[u] = __ldg(reinterpret_cast<const float2*>(base));
            cB[u] = __ldg(reinterpret_cast<const float2*>(base + 64));
        }
        float s[5];
        #pragma unroll
        for (int u = 0; u < 5; u++)
            s[u] = fmaf(neA.x, cA[u].x, fmaf(neA.y, cA[u].y,
                    fmaf(neB.x, cB[u].x, neB.y * cB[u].y)));
        #pragma unroll
        for (int off = 16; off; off >>= 1) {
            #pragma unroll
            for (int u = 0; u < 5; u++)
                s[u] += __shfl_xor_sync(0xffffffffu, s[u], off);
        }
        #pragma unroll
        for (int u = 0; u < 5; u++) a += logsig_fast(NEG ? -s[u] : s[u]);
    }
    return a;
}

__device__ __forceinline__ void block_publish(float acc, int lane, int wid, int slot) {
    __shared__ float sacc[WPB];
    if (lane == 0) sacc[wid] = acc;
    __syncthreads();
    if (threadIdx.x == 0) {
        float t = 0.0f;
        #pragma unroll
        for (int w = 0; w < WPB; w++) t += sacc[w];
        g_part[slot] = t;
    }
}

// ---------------- kernel 1: neigh-table terms (t1, t3), LDG.64-split ----------------
__global__ void __launch_bounds__(NTHREADS)
neigh_kernel(const float* __restrict__ node_tables,
             const float* __restrict__ neigh_tables,
             const int* __restrict__ nodes_idx,
             const int* __restrict__ neigh_idx,
             const int* __restrict__ neg_main,
             const int* __restrict__ neg_cross) {
    const int lane = threadIdx.x & 31;
    const int wid  = threadIdx.x >> 5;
    const int gw   = blockIdx.x * WPB + wid;
    const size_t VD = (size_t)V * D;

    const float CB = 1.0f / (10.0f * (float)B);
    const float WH = 0.1f;

    // block-index ordered: first half targets gt0, second half gt1
    const int g   = gw >> 14;
    const int r   = gw & 16383;
    const int b   = r >> 2;
    const int sub = r & 3;

    const float* gt = neigh_tables + (size_t)g * VD;

    float acc = 0.0f;
    if (sub < 2) {
        // main SGNS of view i=g (weight 1)
        const int nid = __ldg(nodes_idx + g * B + b);
        const float* nb = node_tables + (size_t)g * VD + (size_t)nid * D + 2 * lane;
        const float2 neA = __ldg(reinterpret_cast<const float2*>(nb));
        const float2 neB = __ldg(reinterpret_cast<const float2*>(nb + 64));
        const int* nm = neg_main + (size_t)(g * B + b) * (K * NS);
        if (sub == 0) {
            acc += rows_sum5h<false>(gt, neigh_idx + (g * B + b) * K, K, neA, neB, lane) * (-CB / (float)K);
            acc += rows_sum5h<true>(gt, nm, 25, neA, neB, lane) * (-CB);
        } else {
            acc += rows_sum5h<true>(gt, nm + 25, 25, neA, neB, lane) * (-CB);
        }
    } else {
        // cross neighbor loss of view i=1-g with j=g (weight HYP2)
        const int i = 1 - g;
        const int nid = __ldg(nodes_idx + i * B + b);
        const float* nb = node_tables + (size_t)i * VD + (size_t)nid * D + 2 * lane;
        const float2 neA = __ldg(reinterpret_cast<const float2*>(nb));
        const float2 neB = __ldg(reinterpret_cast<const float2*>(nb + 64));
        const int* nc = neg_cross + (size_t)((i * NUM_NET + g) * B + b) * (K * NS);
        if (sub == 2) {
            acc += rows_sum5h<false>(gt, neigh_idx + (i * B + b) * K, K, neA, neB, lane) * (-WH * CB / (float)K);
            acc += rows_sum5h<true>(gt, nc, 25, neA, neB, lane) * (-WH * CB);
        } else {
            acc += rows_sum5h<true>(gt, nc + 25, 25, neA, neB, lane) * (-WH * CB);
        }
    }

    block_publish(acc, lane, wid, blockIdx.x);
}

// -------- kernel 2: node-table terms (t2, roles) + final reduction (R10 exact) --------
__global__ void __launch_bounds__(NTHREADS)
node_kernel(const float* __restrict__ node_tables,
            const int* __restrict__ nodes_idx,
            const int* __restrict__ role_idx,
            const int* __restrict__ neg_node,
            const int* __restrict__ neg_role,
            float* __restrict__ out) {
    const int lane = threadIdx.x & 31;
    const int wid  = threadIdx.x >> 5;
    const int gw   = blockIdx.x * WPB + wid;
    const size_t VD = (size_t)V * D;

    const float CB = 1.0f / (10.0f * (float)B);
    const float WH = 0.1f;

    // block-index ordered by target node table m
    const int m = gw >> 13;
    const int r = gw & 8191;
    const int i = r >> 12;
    const int b = r & 4095;

    const float* nt = node_tables + (size_t)m * VD;

    const int nid = __ldg(nodes_idx + i * B + b);
    const float4 ne = __ldg(reinterpret_cast<const float4*>(
        node_tables + (size_t)i * VD + (size_t)nid * D) + lane);

    const float w = -WH * CB;
    const int* nr = neg_role + (size_t)((i * NUM_NET + m) * B + b) * NS;
    const int rp  = __ldg(role_idx + (i * NUM_NET + m) * B + b);

    float acc = 0.0f;
    if (m != i) {
        // t2 (pos=nid row in nt_m, 10 negs) + role j2=m (pos + 10 negs)
        acc += pos2(nt, nid, rp, ne, lane) * w;
        acc += rows_sum5<true>(nt, neg_node + (size_t)((i * NUM_NET + m) * B + b) * NS, NS, ne, lane) * w;
        acc += rows_sum5<true>(nt, nr, NS, ne, lane) * w;
    } else {
        // role j2=m=i only
        acc += pos1(nt, rp, ne, lane) * w;
        acc += rows_sum5<true>(nt, nr, NS, ne, lane) * w;
    }

    block_publish(acc, lane, wid, NEIGH_BLOCKS + blockIdx.x);

    // last node-block reduces ALL partials (kernel-1 partials already globally
    // visible: kernel boundary). Fixed read order -> deterministic.
    __shared__ int s_last;
    if (threadIdx.x == 0) {
        __threadfence();
        int c = atomicAdd(&g_count, 1);
        s_last = (c == NODE_BLOCKS - 1);
    }
    __syncthreads();
    if (s_last) {
        __threadfence();
        __shared__ double sh[WPB];
        double t = 0.0;
        for (int k2 = threadIdx.x; k2 < NPART; k2 += NTHREADS)
            t += (double)g_part[k2];
        #pragma unroll
        for (int off = 16; off; off >>= 1)
            t += __shfl_xor_sync(0xffffffffu, t, off);
        if (lane == 0) sh[wid] = t;
        __syncthreads();
        if (threadIdx.x == 0) {
            double v = 0.0;
            #pragma unroll
            for (int ww = 0; ww < WPB; ww++) v += sh[ww];
            out[0] = (float)v;
            g_count = 0;              // reset for next graph replay
        }
    }
}

extern "C" void kernel_launch(void* const* d_in, const int* in_sizes, int n_in,
                              void* d_out, int out_size) {
    const float* node_tables  = (const float*)d_in[0];
    const float* neigh_tables = (const float*)d_in[1];
    const int*   nodes_idx    = (const int*)d_in[2];
    const int*   neigh_idx    = (const int*)d_in[3];
    const int*   role_idx     = (const int*)d_in[4];
    const int*   neg_main     = (const int*)d_in[5];
    const int*   neg_node     = (const int*)d_in[6];
    const int*   neg_cross    = (const int*)d_in[7];
    const int*   neg_role     = (const int*)d_in[8];

    (void)in_sizes; (void)n_in; (void)out_size;

    neigh_kernel<<<NEIGH_BLOCKS, NTHREADS>>>(node_tables, neigh_tables, nodes_idx,
                                             neigh_idx, neg_main, neg_cross);
    node_kernel<<<NODE_BLOCKS, NTHREADS>>>(node_tables, nodes_idx, role_idx,
                                           neg_node, neg_role, (float*)d_out);
}

// round 14
// speedup vs baseline: 1.0354x; 1.0064x over previous
#include <cuda_runtime.h>

#define NUM_NET 2
#define V 100000
#define D 128
#define B 4096
#define K 5
#define NS 10

#define NTHREADS 256
#define WPB 8
#define NEIGH_BLOCKS 4096                  // 32768 warps: 4 per (i,b), table-phased
#define NODE_BLOCKS  2048                  // 16384 warps: 1 per (i,b,m)
#define NBLOCKS (NEIGH_BLOCKS + NODE_BLOCKS)  // 6144, interleaved 2 neigh : 1 node
#define NPART NBLOCKS

__device__ float g_part[NPART];
__device__ int   g_count = 0;

__device__ __forceinline__ float logsig_fast(float x) {
    // log(sigmoid(x)) = min(x,0) - log(1 + exp(-|x|)); fast-math (err ~1e-6 vs 1e-3 budget)
    return fminf(x, 0.0f) - __logf(1.0f + __expf(-fabsf(x)));
}

__device__ __forceinline__ float dot4(float4 a, float4 b) {
    return fmaf(a.x, b.x, fmaf(a.y, b.y, fmaf(a.z, b.z, a.w * b.w)));
}

// Sum of logsig(sign*(row . ne)) over M rows, 5 independent chains per batch.
// The proven 32-reg shape. Do not touch.
template<bool NEG>
__device__ __forceinline__ float rows_sum5(const float* __restrict__ tab,
                                           const int* __restrict__ idx,
                                           int M, float4 ne, int lane) {
    float a = 0.0f;
    for (int m = 0; m < M; m += 5) {
        float4 c[5];
        #pragma unroll
        for (int u = 0; u < 5; u++) {
            int id = __ldg(idx + m + u);
            c[u] = __ldg(reinterpret_cast<const float4*>(tab + (size_t)id * D) + lane);
        }
        float s[5];
        #pragma unroll
        for (int u = 0; u < 5; u++) s[u] = dot4(ne, c[u]);
        #pragma unroll
        for (int off = 16; off; off >>= 1) {
            #pragma unroll
            for (int u = 0; u < 5; u++)
                s[u] += __shfl_xor_sync(0xffffffffu, s[u], off);
        }
        #pragma unroll
        for (int u = 0; u < 5; u++) a += logsig_fast(NEG ? -s[u] : s[u]);
    }
    return a;
}

__device__ __forceinline__ float pos2(const float* __restrict__ tab, int i0, int i1,
                                      float4 ne, int lane) {
    float4 c0 = __ldg(reinterpret_cast<const float4*>(tab + (size_t)i0 * D) + lane);
    float4 c1 = __ldg(reinterpret_cast<const float4*>(tab + (size_t)i1 * D) + lane);
    float s0 = dot4(ne, c0), s1 = dot4(ne, c1);
    #pragma unroll
    for (int off = 16; off; off >>= 1) {
        s0 += __shfl_xor_sync(0xffffffffu, s0, off);
        s1 += __shfl_xor_sync(0xffffffffu, s1, off);
    }
    return logsig_fast(s0) + logsig_fast(s1);
}

__device__ __forceinline__ float pos1(const float* __restrict__ tab, int i0,
                                      float4 ne, int lane) {
    float4 c0 = __ldg(reinterpret_cast<const float4*>(tab + (size_t)i0 * D) + lane);
    float s0 = dot4(ne, c0);
    #pragma unroll
    for (int off = 16; off; off >>= 1)
        s0 += __shfl_xor_sync(0xffffffffu, s0, off);
    return logsig_fast(s0);
}

__global__ void __launch_bounds__(NTHREADS)
loss_kernel(const float* __restrict__ node_tables,
            const float* __restrict__ neigh_tables,
            const int* __restrict__ nodes_idx,
            const int* __restrict__ neigh_idx,
            const int* __restrict__ role_idx,
            const int* __restrict__ neg_main,
            const int* __restrict__ neg_node,
            const int* __restrict__ neg_cross,
            const int* __restrict__ neg_role,
            float* __restrict__ out) {
    const int lane = threadIdx.x & 31;
    const int wid  = threadIdx.x >> 5;
    const size_t VD = (size_t)V * D;

    const float CB = 1.0f / (10.0f * (float)B);
    const float WH = 0.1f;

    // interleave: per block-trio, 2 neigh blocks (LTS-cap bound) + 1 node block
    // (latency bound) so the node work rides in the neigh phase's latency slack.
    const int trio = blockIdx.x / 3;
    const int rsel = blockIdx.x - trio * 3;

    float acc = 0.0f;
    int slot;

    if (rsel < 2) {
        // ================= neigh work (t1, t3) — R10 body =================
        const int nb = trio * 2 + rsel;            // 0 .. 4095
        slot = nb;
        const int gw = nb * WPB + wid;             // 0 .. 32767

        const int g   = gw >> 14;                  // target neigh table
        const int r   = gw & 16383;
        const int b   = r >> 2;
        const int sub = r & 3;

        const float* gt = neigh_tables + (size_t)g * VD;

        if (sub < 2) {
            // main SGNS of view i=g (weight 1)
            const int nid = __ldg(nodes_idx + g * B + b);
            const float4 ne = __ldg(reinterpret_cast<const float4*>(
                node_tables + (size_t)g * VD + (size_t)nid * D) + lane);
            const int* nm = neg_main + (size_t)(g * B + b) * (K * NS);
            if (sub == 0) {
                acc += rows_sum5<false>(gt, neigh_idx + (g * B + b) * K, K, ne, lane) * (-CB / (float)K);
                acc += rows_sum5<true>(gt, nm, 25, ne, lane) * (-CB);
            } else {
                acc += rows_sum5<true>(gt, nm + 25, 25, ne, lane) * (-CB);
            }
        } else {
            // cross neighbor loss of view i=1-g with j=g (weight HYP2)
            const int i = 1 - g;
            const int nid = __ldg(nodes_idx + i * B + b);
            const float4 ne = __ldg(reinterpret_cast<const float4*>(
                node_tables + (size_t)i * VD + (size_t)nid * D) + lane);
            const int* nc = neg_cross + (size_t)((i * NUM_NET + g) * B + b) * (K * NS);
            if (sub == 2) {
                acc += rows_sum5<false>(gt, neigh_idx + (i * B + b) * K, K, ne, lane) * (-WH * CB / (float)K);
                acc += rows_sum5<true>(gt, nc, 25, ne, lane) * (-WH * CB);
            } else {
                acc += rows_sum5<true>(gt, nc + 25, 25, ne, lane) * (-WH * CB);
            }
        }
    } else {
        // ================= node work (t2, roles) — R10 body =================
        const int qb = trio;                       // 0 .. 2047
        slot = NEIGH_BLOCKS + qb;
        const int gw = qb * WPB + wid;             // 0 .. 16383

        const int m = gw >> 13;                    // target node table
        const int r = gw & 8191;
        const int i = r >> 12;
        const int b = r & 4095;

        const float* nt = node_tables + (size_t)m * VD;

        const int nid = __ldg(nodes_idx + i * B + b);
        const float4 ne = __ldg(reinterpret_cast<const float4*>(
            node_tables + (size_t)i * VD + (size_t)nid * D) + lane);

        const float w = -WH * CB;
        const int* nr = neg_role + (size_t)((i * NUM_NET + m) * B + b) * NS;
        const int rp  = __ldg(role_idx + (i * NUM_NET + m) * B + b);

        if (m != i) {
            // t2 (pos=nid row in nt_m, 10 negs) + role j2=m (pos + 10 negs)
            acc += pos2(nt, nid, rp, ne, lane) * w;
            acc += rows_sum5<true>(nt, neg_node + (size_t)((i * NUM_NET + m) * B + b) * NS, NS, ne, lane) * w;
            acc += rows_sum5<true>(nt, nr, NS, ne, lane) * w;
        } else {
            // role j2=m=i only
            acc += pos1(nt, rp, ne, lane) * w;
            acc += rows_sum5<true>(nt, nr, NS, ne, lane) * w;
        }
    }

    __shared__ float sacc[WPB];
    __shared__ int s_last;
    if (lane == 0) sacc[wid] = acc;
    __syncthreads();
    if (threadIdx.x == 0) {
        float t = 0.0f;
        #pragma unroll
        for (int w = 0; w < WPB; w++) t += sacc[w];
        g_part[slot] = t;             // always written: no zero-init needed
        __threadfence();
        int c = atomicAdd(&g_count, 1);
        s_last = (c == NBLOCKS - 1);
    }
    __syncthreads();

    // the last block to arrive reduces all partials; fixed read order -> deterministic
    if (s_last) {
        __threadfence();              // acquire: see all g_part writes
        __shared__ double sh[WPB];
        double t = 0.0;
        for (int k2 = threadIdx.x; k2 < NPART; k2 += NTHREADS)
            t += (double)g_part[k2];
        #pragma unroll
        for (int off = 16; off; off >>= 1)
            t += __shfl_xor_sync(0xffffffffu, t, off);
        if (lane == 0) sh[wid] = t;
        __syncthreads();
        if (threadIdx.x == 0) {
            double v = 0.0;
            #pragma unroll
            for (int ww = 0; ww < WPB; ww++) v += sh[ww];
            out[0] = (float)v;
            g_count = 0;              // reset for next graph replay
        }
    }
}

extern "C" void kernel_launch(void* const* d_in, const int* in_sizes, int n_in,
                              void* d_out, int out_size) {
    const float* node_tables  = (const float*)d_in[0];
    const float* neigh_tables = (const float*)d_in[1];
    const int*   nodes_idx    = (const int*)d_in[2];
    const int*   neigh_idx    = (const int*)d_in[3];
    const int*   role_idx     = (const int*)d_in[4];
    const int*   neg_main     = (const int*)d_in[5];
    const int*   neg_node     = (const int*)d_in[6];
    const int*   neg_cross    = (const int*)d_in[7];
    const int*   neg_role     = (const int*)d_in[8];

    (void)in_sizes; (void)n_in; (void)out_size;

    loss_kernel<<<NBLOCKS, NTHREADS>>>(node_tables, neigh_tables, nodes_idx,
                                       neigh_idx, role_idx, neg_main,
                                       neg_node, neg_cross, neg_role,
                                       (float*)d_out);
}